// round 1
// baseline (speedup 1.0000x reference)
#include <cuda_runtime.h>
#include <math.h>

// ---------------- problem constants ----------------
#define BATCH   64
#define NTOK    197
#define DIMC    768
#define HEADS   12
#define DHEAD   64
#define TTOK    4
#define BV      (BATCH / TTOK)          // 16
#define MROWS   (BATCH * NTOK)          // 12608
#define FDIM    (DIMC * 4)              // 3072
#define NN2     (NTOK * NTOK)           // 38809
#define EPSLN   1e-6f

// ---------------- scratch (device globals, no allocation) ----------------
__device__ float g_h [MROWS * DIMC];                 // LN1 out, reused for LN2 out
__device__ float g_q [BATCH * HEADS * NTOK * DHEAD]; // q + cq
__device__ float g_k [BATCH * HEADS * NTOK * DHEAD]; // k + ck
__device__ float g_v [BATCH * HEADS * NTOK * DHEAD];
__device__ float g_cq[BATCH * DIMC];
__device__ float g_ck[BATCH * DIMC];
__device__ float g_s [(size_t)BATCH * HEADS * NN2];  // scores / probs
__device__ float g_o [MROWS * DIMC];                 // attention out (B,N,C)
__device__ float g_x1[MROWS * DIMC];                 // x + attn branch
__device__ float g_ff[MROWS * FDIM];                 // gelu(ff1)

// ---------------- layernorm ----------------
__global__ __launch_bounds__(256) void ln_kernel(const float* __restrict__ x,
                                                 const float* __restrict__ w,
                                                 const float* __restrict__ b,
                                                 float* __restrict__ out)
{
    int row = blockIdx.x;
    const float* xr = x + (size_t)row * DIMC;
    float s = 0.f, s2 = 0.f;
    float vals[3];
    #pragma unroll
    for (int t = 0; t < 3; t++) {
        float v = xr[threadIdx.x + 256 * t];
        vals[t] = v; s += v; s2 += v * v;
    }
    // block reduce (8 warps)
    __shared__ float shs[8], shs2[8];
    #pragma unroll
    for (int o = 16; o > 0; o >>= 1) {
        s  += __shfl_down_sync(0xffffffffu, s,  o);
        s2 += __shfl_down_sync(0xffffffffu, s2, o);
    }
    if ((threadIdx.x & 31) == 0) { shs[threadIdx.x >> 5] = s; shs2[threadIdx.x >> 5] = s2; }
    __syncthreads();
    __shared__ float sh_mean, sh_rstd;
    if (threadIdx.x == 0) {
        float ts = 0.f, ts2 = 0.f;
        #pragma unroll
        for (int i = 0; i < 8; i++) { ts += shs[i]; ts2 += shs2[i]; }
        float mean = ts / DIMC;
        float var  = ts2 / DIMC - mean * mean;
        sh_mean = mean;
        sh_rstd = rsqrtf(var + EPSLN);
    }
    __syncthreads();
    float mean = sh_mean, rstd = sh_rstd;
    float* orow = out + (size_t)row * DIMC;
    #pragma unroll
    for (int t = 0; t < 3; t++) {
        int i = threadIdx.x + 256 * t;
        orow[i] = (vals[t] - mean) * rstd * w[i] + b[i];
    }
}

// ---------------- conv1d (q and k temporal calibration), warp per output ----------------
__global__ __launch_bounds__(256) void conv_kernel(const float* __restrict__ wq,
                                                   const float* __restrict__ bq,
                                                   const float* __restrict__ wk,
                                                   const float* __restrict__ bk)
{
    int gw   = blockIdx.x * 8 + (threadIdx.x >> 5);
    int lane = threadIdx.x & 31;
    int which = gw / (BATCH * DIMC);
    int rem   = gw % (BATCH * DIMC);
    int bt = rem / DIMC;       // b index = bv*4 + t
    int co = rem % DIMC;
    int bv = bt >> 2, t = bt & 3;
    const float* w  = which ? wk : wq;
    const float* bb = which ? bk : bq;
    float s = 0.f;
    const float* h0 = (t > 0) ? (g_h + (size_t)(bv * 4 + t - 1) * NTOK * DIMC) : nullptr;
    const float* h1 = g_h + (size_t)(bv * 4 + t) * NTOK * DIMC;
    const float* h2 = (t < 3) ? (g_h + (size_t)(bv * 4 + t + 1) * NTOK * DIMC) : nullptr;
    for (int ci = lane; ci < DIMC; ci += 32) {
        const float* wp = w + ((size_t)co * DIMC + ci) * 3;
        float w0 = wp[0], w1 = wp[1], w2 = wp[2];
        if (h0) s += w0 * h0[ci];
        s += w1 * h1[ci];
        if (h2) s += w2 * h2[ci];
    }
    #pragma unroll
    for (int o = 16; o > 0; o >>= 1) s += __shfl_down_sync(0xffffffffu, s, o);
    if (lane == 0) {
        float* dst = which ? g_ck : g_cq;
        dst[bt * DIMC + co] = s + bb[co];
    }
}

// ---------------- generic SGEMM: out[m][n] = A[m][:] . W[n][:] + epilogue ----------------
// MODE 0: QKV scatter (+cq/ck), MODE 1: proj + residual(x), MODE 2: ff1 + gelu, MODE 3: ff2 + residual(g_x1)
#define BM 128
#define BN 128
#define BKK 8

template<int MODE>
__global__ __launch_bounds__(256, 2) void gemm_kernel(const float* __restrict__ A,
                                                      const float* __restrict__ W,
                                                      const float* __restrict__ bias,
                                                      const float* __restrict__ resid,
                                                      float* __restrict__ out,
                                                      int M, int Nn, int K)
{
    __shared__ float As[BKK][BM];
    __shared__ float Bs[BKK][BN];
    int m0 = blockIdx.y * BM;
    int n0 = blockIdx.x * BN;
    int tid = threadIdx.x;
    int arow = tid >> 1;            // 0..127
    int acol = (tid & 1) * 4;       // 0 or 4
    bool a_ok = (m0 + arow) < M;
    const float* Abase = A + (size_t)(m0 + arow) * K + acol;
    const float* Wbase = W + (size_t)(n0 + arow) * K + acol;
    int tr = (tid >> 4) * 8;        // output row within tile
    int tc = (tid & 15) * 8;        // output col within tile
    float acc[8][8];
    #pragma unroll
    for (int i = 0; i < 8; i++)
        #pragma unroll
        for (int j = 0; j < 8; j++) acc[i][j] = 0.f;

    for (int k0 = 0; k0 < K; k0 += BKK) {
        float4 av = a_ok ? *(const float4*)(Abase + k0) : make_float4(0.f,0.f,0.f,0.f);
        float4 bv = *(const float4*)(Wbase + k0);
        As[acol+0][arow] = av.x; As[acol+1][arow] = av.y;
        As[acol+2][arow] = av.z; As[acol+3][arow] = av.w;
        Bs[acol+0][arow] = bv.x; Bs[acol+1][arow] = bv.y;
        Bs[acol+2][arow] = bv.z; Bs[acol+3][arow] = bv.w;
        __syncthreads();
        #pragma unroll
        for (int k = 0; k < BKK; k++) {
            float4 a0 = *(const float4*)&As[k][tr];
            float4 a1 = *(const float4*)&As[k][tr + 4];
            float4 b0 = *(const float4*)&Bs[k][tc];
            float4 b1 = *(const float4*)&Bs[k][tc + 4];
            float ra[8] = {a0.x,a0.y,a0.z,a0.w,a1.x,a1.y,a1.z,a1.w};
            float rb[8] = {b0.x,b0.y,b0.z,b0.w,b1.x,b1.y,b1.z,b1.w};
            #pragma unroll
            for (int i = 0; i < 8; i++)
                #pragma unroll
                for (int j = 0; j < 8; j++) acc[i][j] += ra[i] * rb[j];
        }
        __syncthreads();
    }

    #pragma unroll
    for (int i = 0; i < 8; i++) {
        int m = m0 + tr + i;
        if (m >= M) continue;
        int bIdx = m / NTOK, nIdx = m % NTOK;     // used by MODE 0
        #pragma unroll
        for (int j = 0; j < 8; j++) {
            int col = n0 + tc + j;
            float v = acc[i][j] + bias[col];
            if (MODE == 0) {
                int which = col / DIMC;
                int r = col % DIMC;
                int hh = r >> 6, d = r & 63;
                size_t dst = ((size_t)(bIdx * HEADS + hh) * NTOK + nIdx) * DHEAD + d;
                if      (which == 0) g_q[dst] = v + g_cq[bIdx * DIMC + r];
                else if (which == 1) g_k[dst] = v + g_ck[bIdx * DIMC + r];
                else                 g_v[dst] = v;
            } else if (MODE == 1) {
                size_t idx = (size_t)m * DIMC + col;
                out[idx] = v + resid[idx];
            } else if (MODE == 2) {
                out[(size_t)m * FDIM + col] = 0.5f * v * (1.0f + erff(v * 0.70710678118654752f));
            } else {
                size_t idx = (size_t)m * DIMC + col;
                out[idx] = v + g_x1[idx];
            }
        }
    }
}

// ---------------- attention scores: S = (q+cq)(k+ck)^T * scale ----------------
__global__ __launch_bounds__(256) void scores_kernel()
{
    int bh = blockIdx.x;
    int n0 = blockIdx.y * 32;
    int m0 = blockIdx.z * 32;
    __shared__ float Qs[32][64];
    __shared__ float Ks[32][65];
    const float* Q = g_q + (size_t)bh * NTOK * DHEAD;
    const float* Kk = g_k + (size_t)bh * NTOK * DHEAD;
    int tid = threadIdx.x;
    for (int idx = tid; idx < 32 * 64; idx += 256) {
        int r = idx >> 6, c = idx & 63;
        Qs[r][c] = (n0 + r < NTOK) ? Q[(n0 + r) * DHEAD + c] : 0.f;
        Ks[r][c] = (m0 + r < NTOK) ? Kk[(m0 + r) * DHEAD + c] : 0.f;
    }
    __syncthreads();
    int j  = tid & 31;
    int i0 = tid >> 5;    // 0..7
    float acc[4] = {0.f, 0.f, 0.f, 0.f};
    #pragma unroll 8
    for (int d = 0; d < 64; d++) {
        float kv = Ks[j][d];
        #pragma unroll
        for (int r = 0; r < 4; r++) acc[r] += Qs[i0 + 8 * r][d] * kv;
    }
    #pragma unroll
    for (int r = 0; r < 4; r++) {
        int n = n0 + i0 + 8 * r;
        int m = m0 + j;
        if (n < NTOK && m < NTOK)
            g_s[(size_t)bh * NN2 + (size_t)n * NTOK + m] = acc[r] * 0.125f;
    }
}

// ---------------- softmax over keys (197) ----------------
__global__ __launch_bounds__(128) void softmax_kernel()
{
    size_t row = blockIdx.x;
    float* r = g_s + row * NTOK;
    int tid = threadIdx.x;
    float v0 = r[tid];
    float v1 = (tid + 128 < NTOK) ? r[tid + 128] : -1e30f;
    float mx = fmaxf(v0, v1);
    __shared__ float sh[4];
    #pragma unroll
    for (int o = 16; o > 0; o >>= 1) mx = fmaxf(mx, __shfl_down_sync(0xffffffffu, mx, o));
    if ((tid & 31) == 0) sh[tid >> 5] = mx;
    __syncthreads();
    __shared__ float shm, shsum;
    if (tid == 0) shm = fmaxf(fmaxf(sh[0], sh[1]), fmaxf(sh[2], sh[3]));
    __syncthreads();
    mx = shm;
    float e0 = expf(v0 - mx);
    float e1 = (tid + 128 < NTOK) ? expf(v1 - mx) : 0.f;
    float s = e0 + e1;
    #pragma unroll
    for (int o = 16; o > 0; o >>= 1) s += __shfl_down_sync(0xffffffffu, s, o);
    if ((tid & 31) == 0) sh[tid >> 5] = s;
    __syncthreads();
    if (tid == 0) shsum = sh[0] + sh[1] + sh[2] + sh[3];
    __syncthreads();
    float inv = 1.0f / shsum;
    r[tid] = e0 * inv;
    if (tid + 128 < NTOK) r[tid + 128] = e1 * inv;
}

// ---------------- O = P @ V, written as (B,N,C) ----------------
__global__ __launch_bounds__(256) void av_kernel()
{
    int bh = blockIdx.x;
    int b = bh / HEADS, h = bh % HEADS;
    int n0 = blockIdx.y * 32;
    __shared__ float Ps[32][33];
    __shared__ float Vs[32][64];
    const float* P = g_s + (size_t)bh * NN2;
    const float* V = g_v + (size_t)bh * NTOK * DHEAD;
    int tid = threadIdx.x;
    int d  = tid & 63;
    int ib = tid >> 6;    // 0..3
    float acc[8] = {0.f,0.f,0.f,0.f,0.f,0.f,0.f,0.f};
    for (int m0 = 0; m0 < NTOK; m0 += 32) {
        for (int idx = tid; idx < 32 * 32; idx += 256) {
            int r = idx >> 5, c = idx & 31;
            Ps[r][c] = (n0 + r < NTOK && m0 + c < NTOK)
                       ? P[(size_t)(n0 + r) * NTOK + m0 + c] : 0.f;
        }
        for (int idx = tid; idx < 32 * 64; idx += 256) {
            int r = idx >> 6, c = idx & 63;
            Vs[r][c] = (m0 + r < NTOK) ? V[(m0 + r) * DHEAD + c] : 0.f;
        }
        __syncthreads();
        #pragma unroll 8
        for (int mm = 0; mm < 32; mm++) {
            float vv = Vs[mm][d];
            #pragma unroll
            for (int r = 0; r < 8; r++) acc[r] += Ps[ib + 4 * r][mm] * vv;
        }
        __syncthreads();
    }
    #pragma unroll
    for (int r = 0; r < 8; r++) {
        int n = n0 + ib + 4 * r;
        if (n < NTOK)
            g_o[(size_t)(b * NTOK + n) * DIMC + h * DHEAD + d] = acc[r];
    }
}

// ---------------- launch ----------------
extern "C" void kernel_launch(void* const* d_in, const int* in_sizes, int n_in,
                              void* d_out, int out_size)
{
    const float* x      = (const float*)d_in[0];
    const float* ln1_w  = (const float*)d_in[1];
    const float* ln1_b  = (const float*)d_in[2];
    const float* qkv_w  = (const float*)d_in[3];
    const float* qkv_b  = (const float*)d_in[4];
    const float* convq_w= (const float*)d_in[5];
    const float* convq_b= (const float*)d_in[6];
    const float* convk_w= (const float*)d_in[7];
    const float* convk_b= (const float*)d_in[8];
    const float* proj_w = (const float*)d_in[9];
    const float* proj_b = (const float*)d_in[10];
    const float* ln2_w  = (const float*)d_in[11];
    const float* ln2_b  = (const float*)d_in[12];
    const float* ff1_w  = (const float*)d_in[13];
    const float* ff1_b  = (const float*)d_in[14];
    const float* ff2_w  = (const float*)d_in[15];
    const float* ff2_b  = (const float*)d_in[16];
    float* out = (float*)d_out;

    float* p_h;  cudaGetSymbolAddress((void**)&p_h,  g_h);
    float* p_o;  cudaGetSymbolAddress((void**)&p_o,  g_o);
    float* p_x1; cudaGetSymbolAddress((void**)&p_x1, g_x1);
    float* p_ff; cudaGetSymbolAddress((void**)&p_ff, g_ff);

    // 1. LN1
    ln_kernel<<<MROWS, 256>>>(x, ln1_w, ln1_b, p_h);
    // 2. temporal conv on per-frame CLS tokens
    conv_kernel<<<(2 * BATCH * DIMC) / 8, 256>>>(convq_w, convq_b, convk_w, convk_b);
    // 3. QKV GEMM (+bias, +cq/ck, scatter to head layout)
    gemm_kernel<0><<<dim3(3 * DIMC / BN, (MROWS + BM - 1) / BM), 256>>>(
        p_h, qkv_w, qkv_b, nullptr, nullptr, MROWS, 3 * DIMC, DIMC);
    // 4. scores
    scores_kernel<<<dim3(BATCH * HEADS, 7, 7), 256>>>();
    // 5. softmax
    softmax_kernel<<<BATCH * HEADS * NTOK, 128>>>();
    // 6. P @ V
    av_kernel<<<dim3(BATCH * HEADS, 7), 256>>>();
    // 7. proj + residual
    gemm_kernel<1><<<dim3(DIMC / BN, (MROWS + BM - 1) / BM), 256>>>(
        p_o, proj_w, proj_b, x, p_x1, MROWS, DIMC, DIMC);
    // 8. LN2
    ln_kernel<<<MROWS, 256>>>(p_x1, ln2_w, ln2_b, p_h);
    // 9. FF1 + GELU
    gemm_kernel<2><<<dim3(FDIM / BN, (MROWS + BM - 1) / BM), 256>>>(
        p_h, ff1_w, ff1_b, nullptr, p_ff, MROWS, FDIM, DIMC);
    // 10. FF2 + residual -> out
    gemm_kernel<3><<<dim3(DIMC / BN, (MROWS + BM - 1) / BM), 256>>>(
        p_ff, ff2_w, ff2_b, nullptr, out, MROWS, DIMC, FDIM);
}

// round 3
// speedup vs baseline: 1.9861x; 1.9861x over previous
#include <cuda_runtime.h>
#include <math.h>
#include <stdint.h>

// ---------------- problem constants ----------------
#define BATCH   64
#define NTOK    197
#define DIMC    768
#define HEADS   12
#define DHEAD   64
#define MROWS   (BATCH * NTOK)          // 12608
#define FDIM    (DIMC * 4)              // 3072
#define NN2     (NTOK * NTOK)           // 38809
#define EPSLN   1e-6f

// ---------------- scratch (device globals, no allocation) ----------------
__device__ float g_h [MROWS * DIMC];                 // LN1 out, reused for LN2 out
__device__ float g_q [BATCH * HEADS * NTOK * DHEAD]; // q + cq
__device__ float g_k [BATCH * HEADS * NTOK * DHEAD]; // k + ck
__device__ float g_v [BATCH * HEADS * NTOK * DHEAD];
__device__ float g_cq[BATCH * DIMC];
__device__ float g_ck[BATCH * DIMC];
__device__ float g_s [(size_t)BATCH * HEADS * NN2];  // scores / probs
__device__ float g_o [MROWS * DIMC];                 // attention out (B,N,C)
__device__ float g_x1[MROWS * DIMC];                 // x + attn branch
__device__ float g_ff[MROWS * FDIM];                 // gelu(ff1)

// ================= tf32 mma.sync GEMM =================
// D[m][n] = sum_k A[m][k] * W[n][k]  (both row-major, K contiguous)
// MODE 0: QKV scatter (+cq/ck), MODE 1: proj + resid, MODE 2: ff1 + gelu, MODE 3: ff2 + resid

#define TBM 128
#define TBN 128
#define TBK 32
#define TPAD 36                          // stride in elements (bank-conflict-free)
#define A_BUF_BYTES (TBM * TPAD * 4)     // 18432
#define SMEM_A(b) ((b) * A_BUF_BYTES)
#define SMEM_B(b) (2 * A_BUF_BYTES + (b) * A_BUF_BYTES)
#define TC_SMEM   (4 * A_BUF_BYTES)      // 73728

__device__ __forceinline__ uint32_t f2tf32(float v) {
    uint32_t o;
    asm("cvt.rn.tf32.f32 %0, %1;" : "=r"(o) : "f"(v));
    return o;
}

__device__ __forceinline__ void mma_tf32(float* d, const uint32_t* a, const uint32_t* b) {
    asm volatile(
        "mma.sync.aligned.m16n8k8.row.col.f32.tf32.tf32.f32 "
        "{%0,%1,%2,%3}, {%4,%5,%6,%7}, {%8,%9}, {%0,%1,%2,%3};"
        : "+f"(d[0]), "+f"(d[1]), "+f"(d[2]), "+f"(d[3])
        : "r"(a[0]), "r"(a[1]), "r"(a[2]), "r"(a[3]), "r"(b[0]), "r"(b[1]));
}

template<int MODE>
__global__ __launch_bounds__(256)
void tc_gemm(const float* __restrict__ A, const float* __restrict__ W,
             const float* __restrict__ bias, const float* __restrict__ resid,
             float* __restrict__ out, int M, int K)
{
    extern __shared__ char smem[];
    const int tid = threadIdx.x;
    const int wid = tid >> 5, lane = tid & 31;
    const int qr = lane >> 2, qc = lane & 3;
    const int wm = wid >> 2, wn = wid & 3;          // 2 x 4 warp grid
    const int m0 = blockIdx.y * TBM, n0 = blockIdx.x * TBN;

    // staging coords: each thread stages one half-row (16 floats) of A and of B
    const int sr  = tid >> 1;          // 0..127
    const int sub = tid & 1;           // 0 / 1
    const bool aok = (m0 + sr) < M;
    const float* ap = A + (size_t)(m0 + sr) * K + sub * 16;
    const float* bp = W + (size_t)(n0 + sr) * K + sub * 16;

    float acc[4][4][4];
    #pragma unroll
    for (int i = 0; i < 4; i++)
        #pragma unroll
        for (int j = 0; j < 4; j++)
            #pragma unroll
            for (int t = 0; t < 4; t++) acc[i][j][t] = 0.f;

    float4 ra[4], rb[4];
    const int NC = K / TBK;

    // prologue: chunk 0
    #pragma unroll
    for (int q = 0; q < 4; q++) {
        ra[q] = aok ? *(const float4*)(ap + q * 4) : make_float4(0.f,0.f,0.f,0.f);
        rb[q] = *(const float4*)(bp + q * 4);
    }
    {
        uint32_t* sa = (uint32_t*)(smem + SMEM_A(0));
        uint32_t* sb = (uint32_t*)(smem + SMEM_B(0));
        #pragma unroll
        for (int q = 0; q < 4; q++) {
            int o = sr * TPAD + sub * 16 + q * 4;
            sa[o+0]=f2tf32(ra[q].x); sa[o+1]=f2tf32(ra[q].y); sa[o+2]=f2tf32(ra[q].z); sa[o+3]=f2tf32(ra[q].w);
            sb[o+0]=f2tf32(rb[q].x); sb[o+1]=f2tf32(rb[q].y); sb[o+2]=f2tf32(rb[q].z); sb[o+3]=f2tf32(rb[q].w);
        }
    }
    __syncthreads();

    for (int c = 0; c < NC; c++) {
        // issue next chunk's global loads early
        if (c + 1 < NC) {
            const float* apn = ap + (c + 1) * TBK;
            const float* bpn = bp + (c + 1) * TBK;
            #pragma unroll
            for (int q = 0; q < 4; q++) {
                ra[q] = aok ? *(const float4*)(apn + q * 4) : make_float4(0.f,0.f,0.f,0.f);
                rb[q] = *(const float4*)(bpn + q * 4);
            }
        }
        // compute on current buffer
        {
            const uint32_t* sa = (const uint32_t*)(smem + SMEM_A(c & 1));
            const uint32_t* sb = (const uint32_t*)(smem + SMEM_B(c & 1));
            #pragma unroll
            for (int ks = 0; ks < 4; ks++) {
                const int k = ks * 8;
                uint32_t afr[4][4], bfr[4][2];
                #pragma unroll
                for (int mt = 0; mt < 4; mt++) {
                    int row = wm * 64 + mt * 16 + qr;
                    afr[mt][0] = sa[(row    ) * TPAD + k + qc];
                    afr[mt][1] = sa[(row + 8) * TPAD + k + qc];
                    afr[mt][2] = sa[(row    ) * TPAD + k + qc + 4];
                    afr[mt][3] = sa[(row + 8) * TPAD + k + qc + 4];
                }
                #pragma unroll
                for (int nt = 0; nt < 4; nt++) {
                    int cn = wn * 32 + nt * 8 + qr;
                    bfr[nt][0] = sb[cn * TPAD + k + qc];
                    bfr[nt][1] = sb[cn * TPAD + k + qc + 4];
                }
                #pragma unroll
                for (int mt = 0; mt < 4; mt++)
                    #pragma unroll
                    for (int nt = 0; nt < 4; nt++)
                        mma_tf32(acc[mt][nt], afr[mt], bfr[nt]);
            }
        }
        // stage next chunk into the other buffer
        if (c + 1 < NC) {
            uint32_t* sa = (uint32_t*)(smem + SMEM_A((c + 1) & 1));
            uint32_t* sb = (uint32_t*)(smem + SMEM_B((c + 1) & 1));
            #pragma unroll
            for (int q = 0; q < 4; q++) {
                int o = sr * TPAD + sub * 16 + q * 4;
                sa[o+0]=f2tf32(ra[q].x); sa[o+1]=f2tf32(ra[q].y); sa[o+2]=f2tf32(ra[q].z); sa[o+3]=f2tf32(ra[q].w);
                sb[o+0]=f2tf32(rb[q].x); sb[o+1]=f2tf32(rb[q].y); sb[o+2]=f2tf32(rb[q].z); sb[o+3]=f2tf32(rb[q].w);
            }
        }
        __syncthreads();
    }

    // ---- epilogue: direct stores with fused op ----
    #pragma unroll
    for (int mt = 0; mt < 4; mt++) {
        int mA = m0 + wm * 64 + mt * 16 + qr;
        #pragma unroll
        for (int nt = 0; nt < 4; nt++) {
            int col = n0 + wn * 32 + nt * 8 + 2 * qc;
            float2 b2 = *(const float2*)&bias[col];
            #pragma unroll
            for (int half = 0; half < 2; half++) {
                int m = mA + half * 8;
                if (m >= M) continue;
                float v0 = acc[mt][nt][half * 2 + 0] + b2.x;
                float v1 = acc[mt][nt][half * 2 + 1] + b2.y;
                if (MODE == 0) {
                    int which = col / DIMC;
                    int r = col - which * DIMC;
                    int bI = m / NTOK, nI = m - bI * NTOK;
                    int h = r >> 6, d = r & 63;
                    float* dst;
                    if (which == 0) {
                        float2 c2 = *(const float2*)&g_cq[bI * DIMC + r];
                        v0 += c2.x; v1 += c2.y; dst = g_q;
                    } else if (which == 1) {
                        float2 c2 = *(const float2*)&g_ck[bI * DIMC + r];
                        v0 += c2.x; v1 += c2.y; dst = g_k;
                    } else dst = g_v;
                    float2 o2 = make_float2(v0, v1);
                    *(float2*)&dst[((size_t)(bI * HEADS + h) * NTOK + nI) * DHEAD + d] = o2;
                } else if (MODE == 1 || MODE == 3) {
                    size_t ix = (size_t)m * DIMC + col;
                    float2 r2 = *(const float2*)&resid[ix];
                    *(float2*)&out[ix] = make_float2(v0 + r2.x, v1 + r2.y);
                } else { // MODE 2: gelu
                    v0 = 0.5f * v0 * (1.0f + erff(v0 * 0.70710678118654752f));
                    v1 = 0.5f * v1 * (1.0f + erff(v1 * 0.70710678118654752f));
                    *(float2*)&out[(size_t)m * FDIM + col] = make_float2(v0, v1);
                }
            }
        }
    }
}

// ---------------- layernorm ----------------
__global__ __launch_bounds__(256) void ln_kernel(const float* __restrict__ x,
                                                 const float* __restrict__ w,
                                                 const float* __restrict__ b,
                                                 float* __restrict__ out)
{
    int row = blockIdx.x;
    const float* xr = x + (size_t)row * DIMC;
    float s = 0.f, s2 = 0.f;
    float vals[3];
    #pragma unroll
    for (int t = 0; t < 3; t++) {
        float v = xr[threadIdx.x + 256 * t];
        vals[t] = v; s += v; s2 += v * v;
    }
    __shared__ float shs[8], shs2[8];
    #pragma unroll
    for (int o = 16; o > 0; o >>= 1) {
        s  += __shfl_down_sync(0xffffffffu, s,  o);
        s2 += __shfl_down_sync(0xffffffffu, s2, o);
    }
    if ((threadIdx.x & 31) == 0) { shs[threadIdx.x >> 5] = s; shs2[threadIdx.x >> 5] = s2; }
    __syncthreads();
    __shared__ float sh_mean, sh_rstd;
    if (threadIdx.x == 0) {
        float ts = 0.f, ts2 = 0.f;
        #pragma unroll
        for (int i = 0; i < 8; i++) { ts += shs[i]; ts2 += shs2[i]; }
        float mean = ts / DIMC;
        float var  = ts2 / DIMC - mean * mean;
        sh_mean = mean;
        sh_rstd = rsqrtf(var + EPSLN);
    }
    __syncthreads();
    float mean = sh_mean, rstd = sh_rstd;
    float* orow = out + (size_t)row * DIMC;
    #pragma unroll
    for (int t = 0; t < 3; t++) {
        int i = threadIdx.x + 256 * t;
        orow[i] = (vals[t] - mean) * rstd * w[i] + b[i];
    }
}

// ---------------- conv1d (temporal calibration), warp per output ----------------
__global__ __launch_bounds__(256) void conv_kernel(const float* __restrict__ wq,
                                                   const float* __restrict__ bq,
                                                   const float* __restrict__ wk,
                                                   const float* __restrict__ bk)
{
    int gw   = blockIdx.x * 8 + (threadIdx.x >> 5);
    int lane = threadIdx.x & 31;
    int which = gw / (BATCH * DIMC);
    int rem   = gw % (BATCH * DIMC);
    int bt = rem / DIMC;
    int co = rem % DIMC;
    int bv = bt >> 2, t = bt & 3;
    const float* w  = which ? wk : wq;
    const float* bb = which ? bk : bq;
    float s = 0.f;
    const float* h0 = (t > 0) ? (g_h + (size_t)(bv * 4 + t - 1) * NTOK * DIMC) : nullptr;
    const float* h1 = g_h + (size_t)(bv * 4 + t) * NTOK * DIMC;
    const float* h2 = (t < 3) ? (g_h + (size_t)(bv * 4 + t + 1) * NTOK * DIMC) : nullptr;
    for (int ci = lane; ci < DIMC; ci += 32) {
        const float* wp = w + ((size_t)co * DIMC + ci) * 3;
        float w0 = wp[0], w1 = wp[1], w2 = wp[2];
        if (h0) s += w0 * h0[ci];
        s += w1 * h1[ci];
        if (h2) s += w2 * h2[ci];
    }
    #pragma unroll
    for (int o = 16; o > 0; o >>= 1) s += __shfl_down_sync(0xffffffffu, s, o);
    if (lane == 0) {
        float* dst = which ? g_ck : g_cq;
        dst[bt * DIMC + co] = s + bb[co];
    }
}

// ---------------- attention scores ----------------
__global__ __launch_bounds__(256) void scores_kernel()
{
    int bh = blockIdx.x;
    int n0 = blockIdx.y * 32;
    int m0 = blockIdx.z * 32;
    __shared__ float Qs[32][64];
    __shared__ float Ks[32][65];
    const float* Q = g_q + (size_t)bh * NTOK * DHEAD;
    const float* Kk = g_k + (size_t)bh * NTOK * DHEAD;
    int tid = threadIdx.x;
    for (int idx = tid; idx < 32 * 64; idx += 256) {
        int r = idx >> 6, c = idx & 63;
        Qs[r][c] = (n0 + r < NTOK) ? Q[(n0 + r) * DHEAD + c] : 0.f;
        Ks[r][c] = (m0 + r < NTOK) ? Kk[(m0 + r) * DHEAD + c] : 0.f;
    }
    __syncthreads();
    int j  = tid & 31;
    int i0 = tid >> 5;
    float acc[4] = {0.f, 0.f, 0.f, 0.f};
    #pragma unroll 8
    for (int d = 0; d < 64; d++) {
        float kv = Ks[j][d];
        #pragma unroll
        for (int r = 0; r < 4; r++) acc[r] += Qs[i0 + 8 * r][d] * kv;
    }
    #pragma unroll
    for (int r = 0; r < 4; r++) {
        int n = n0 + i0 + 8 * r;
        int m = m0 + j;
        if (n < NTOK && m < NTOK)
            g_s[(size_t)bh * NN2 + (size_t)n * NTOK + m] = acc[r] * 0.125f;
    }
}

// ---------------- softmax over keys ----------------
__global__ __launch_bounds__(128) void softmax_kernel()
{
    size_t row = blockIdx.x;
    float* r = g_s + row * NTOK;
    int tid = threadIdx.x;
    float v0 = r[tid];
    float v1 = (tid + 128 < NTOK) ? r[tid + 128] : -1e30f;
    float mx = fmaxf(v0, v1);
    __shared__ float sh[4];
    #pragma unroll
    for (int o = 16; o > 0; o >>= 1) mx = fmaxf(mx, __shfl_down_sync(0xffffffffu, mx, o));
    if ((tid & 31) == 0) sh[tid >> 5] = mx;
    __syncthreads();
    __shared__ float shm, shsum;
    if (tid == 0) shm = fmaxf(fmaxf(sh[0], sh[1]), fmaxf(sh[2], sh[3]));
    __syncthreads();
    mx = shm;
    float e0 = expf(v0 - mx);
    float e1 = (tid + 128 < NTOK) ? expf(v1 - mx) : 0.f;
    float s = e0 + e1;
    #pragma unroll
    for (int o = 16; o > 0; o >>= 1) s += __shfl_down_sync(0xffffffffu, s, o);
    if ((tid & 31) == 0) sh[tid >> 5] = s;
    __syncthreads();
    if (tid == 0) shsum = sh[0] + sh[1] + sh[2] + sh[3];
    __syncthreads();
    float inv = 1.0f / shsum;
    r[tid] = e0 * inv;
    if (tid + 128 < NTOK) r[tid + 128] = e1 * inv;
}

// ---------------- O = P @ V ----------------
__global__ __launch_bounds__(256) void av_kernel()
{
    int bh = blockIdx.x;
    int b = bh / HEADS, h = bh % HEADS;
    int n0 = blockIdx.y * 32;
    __shared__ float Ps[32][33];
    __shared__ float Vs[32][64];
    const float* P = g_s + (size_t)bh * NN2;
    const float* V = g_v + (size_t)bh * NTOK * DHEAD;
    int tid = threadIdx.x;
    int d  = tid & 63;
    int ib = tid >> 6;
    float acc[8] = {0.f,0.f,0.f,0.f,0.f,0.f,0.f,0.f};
    for (int m0 = 0; m0 < NTOK; m0 += 32) {
        for (int idx = tid; idx < 32 * 32; idx += 256) {
            int r = idx >> 5, c = idx & 31;
            Ps[r][c] = (n0 + r < NTOK && m0 + c < NTOK)
                       ? P[(size_t)(n0 + r) * NTOK + m0 + c] : 0.f;
        }
        for (int idx = tid; idx < 32 * 64; idx += 256) {
            int r = idx >> 6, c = idx & 63;
            Vs[r][c] = (m0 + r < NTOK) ? V[(m0 + r) * DHEAD + c] : 0.f;
        }
        __syncthreads();
        #pragma unroll 8
        for (int mm = 0; mm < 32; mm++) {
            float vv = Vs[mm][d];
            #pragma unroll
            for (int r = 0; r < 8; r++) acc[r] += Ps[ib + 4 * r][mm] * vv;
        }
        __syncthreads();
    }
    #pragma unroll
    for (int r = 0; r < 8; r++) {
        int n = n0 + ib + 4 * r;
        if (n < NTOK)
            g_o[(size_t)(b * NTOK + n) * DIMC + h * DHEAD + d] = acc[r];
    }
}

// ---------------- launch ----------------
extern "C" void kernel_launch(void* const* d_in, const int* in_sizes, int n_in,
                              void* d_out, int out_size)
{
    const float* x      = (const float*)d_in[0];
    const float* ln1_w  = (const float*)d_in[1];
    const float* ln1_b  = (const float*)d_in[2];
    const float* qkv_w  = (const float*)d_in[3];
    const float* qkv_b  = (const float*)d_in[4];
    const float* convq_w= (const float*)d_in[5];
    const float* convq_b= (const float*)d_in[6];
    const float* convk_w= (const float*)d_in[7];
    const float* convk_b= (const float*)d_in[8];
    const float* proj_w = (const float*)d_in[9];
    const float* proj_b = (const float*)d_in[10];
    const float* ln2_w  = (const float*)d_in[11];
    const float* ln2_b  = (const float*)d_in[12];
    const float* ff1_w  = (const float*)d_in[13];
    const float* ff1_b  = (const float*)d_in[14];
    const float* ff2_w  = (const float*)d_in[15];
    const float* ff2_b  = (const float*)d_in[16];
    float* out = (float*)d_out;

    float* p_h;  cudaGetSymbolAddress((void**)&p_h,  g_h);
    float* p_o;  cudaGetSymbolAddress((void**)&p_o,  g_o);
    float* p_x1; cudaGetSymbolAddress((void**)&p_x1, g_x1);
    float* p_ff; cudaGetSymbolAddress((void**)&p_ff, g_ff);

    cudaFuncSetAttribute(tc_gemm<0>, cudaFuncAttributeMaxDynamicSharedMemorySize, TC_SMEM);
    cudaFuncSetAttribute(tc_gemm<1>, cudaFuncAttributeMaxDynamicSharedMemorySize, TC_SMEM);
    cudaFuncSetAttribute(tc_gemm<2>, cudaFuncAttributeMaxDynamicSharedMemorySize, TC_SMEM);
    cudaFuncSetAttribute(tc_gemm<3>, cudaFuncAttributeMaxDynamicSharedMemorySize, TC_SMEM);

    const int MT = (MROWS + TBM - 1) / TBM;   // 99

    // 1. LN1
    ln_kernel<<<MROWS, 256>>>(x, ln1_w, ln1_b, p_h);
    // 2. temporal conv on per-frame CLS tokens
    conv_kernel<<<(2 * BATCH * DIMC) / 8, 256>>>(convq_w, convq_b, convk_w, convk_b);
    // 3. QKV GEMM + scatter to head layout (+cq/ck)
    tc_gemm<0><<<dim3(3 * DIMC / TBN, MT), 256, TC_SMEM>>>(
        p_h, qkv_w, qkv_b, nullptr, nullptr, MROWS, DIMC);
    // 4. scores
    scores_kernel<<<dim3(BATCH * HEADS, 7, 7), 256>>>();
    // 5. softmax
    softmax_kernel<<<BATCH * HEADS * NTOK, 128>>>();
    // 6. P @ V
    av_kernel<<<dim3(BATCH * HEADS, 7), 256>>>();
    // 7. proj + residual
    tc_gemm<1><<<dim3(DIMC / TBN, MT), 256, TC_SMEM>>>(
        p_o, proj_w, proj_b, x, p_x1, MROWS, DIMC);
    // 8. LN2
    ln_kernel<<<MROWS, 256>>>(p_x1, ln2_w, ln2_b, p_h);
    // 9. FF1 + GELU
    tc_gemm<2><<<dim3(FDIM / TBN, MT), 256, TC_SMEM>>>(
        p_h, ff1_w, ff1_b, nullptr, p_ff, MROWS, DIMC);
    // 10. FF2 + residual -> out
    tc_gemm<3><<<dim3(DIMC / TBN, MT), 256, TC_SMEM>>>(
        p_ff, ff2_w, ff2_b, p_x1, out, MROWS, FDIM);
}

// round 4
// speedup vs baseline: 2.6661x; 1.3424x over previous
#include <cuda_runtime.h>
#include <math.h>
#include <stdint.h>

// ---------------- problem constants ----------------
#define BATCH   64
#define NTOK    197
#define DIMC    768
#define HEADS   12
#define DHEAD   64
#define MROWS   (BATCH * NTOK)          // 12608
#define FDIM    (DIMC * 4)              // 3072
#define EPSLN   1e-6f

#define W_QKV_OFF  0
#define W_PROJ_OFF (3 * DIMC * DIMC)                     // 1769472
#define W_FF1_OFF  (W_PROJ_OFF + DIMC * DIMC)            // 2359296
#define W_FF2_OFF  (W_FF1_OFF + FDIM * DIMC)             // 4718592
#define W_TOTAL    (W_FF2_OFF + DIMC * FDIM)             // 7077888

// ---------------- scratch (device globals, no allocation) ----------------
__device__ float g_h  [MROWS * DIMC];                 // LN out (tf32-rounded)
__device__ float g_q  [BATCH * HEADS * NTOK * DHEAD]; // q + cq (tf32-rounded)
__device__ float g_k  [BATCH * HEADS * NTOK * DHEAD]; // k + ck (tf32-rounded)
__device__ float g_v  [BATCH * HEADS * NTOK * DHEAD]; // v (tf32-rounded)
__device__ float g_cq [BATCH * DIMC];
__device__ float g_ck [BATCH * DIMC];
__device__ float g_o  [MROWS * DIMC];                 // attn out (tf32-rounded)
__device__ float g_x1 [MROWS * DIMC];                 // x + attn branch (full fp32)
__device__ float g_ff [MROWS * FDIM];                 // gelu(ff1) (tf32-rounded)
__device__ float g_wts[W_TOTAL];                      // tf32-rounded weights

// ================= helpers =================
__device__ __forceinline__ uint32_t f2tf32(float v) {
    uint32_t o;
    asm("cvt.rn.tf32.f32 %0, %1;" : "=r"(o) : "f"(v));
    return o;
}
__device__ __forceinline__ float rnd_tf32(float v) { return __uint_as_float(f2tf32(v)); }

__device__ __forceinline__ void mma_tf32(float* d, const uint32_t* a, const uint32_t* b) {
    asm volatile(
        "mma.sync.aligned.m16n8k8.row.col.f32.tf32.tf32.f32 "
        "{%0,%1,%2,%3}, {%4,%5,%6,%7}, {%8,%9}, {%0,%1,%2,%3};"
        : "+f"(d[0]), "+f"(d[1]), "+f"(d[2]), "+f"(d[3])
        : "r"(a[0]), "r"(a[1]), "r"(a[2]), "r"(a[3]), "r"(b[0]), "r"(b[1]));
}
__device__ __forceinline__ uint32_t smem_u32(const void* p) {
    uint32_t a;
    asm("{ .reg .u64 t; cvta.to.shared.u64 t, %1; cvt.u32.u64 %0, t; }" : "=r"(a) : "l"(p));
    return a;
}
__device__ __forceinline__ void cpa16(uint32_t dst, const float* src, int sz) {
    asm volatile("cp.async.cg.shared.global [%0], [%1], 16, %2;" :: "r"(dst), "l"(src), "r"(sz));
}
#define CP_COMMIT asm volatile("cp.async.commit_group;" ::: "memory")
#define CP_WAIT1  asm volatile("cp.async.wait_group 1;" ::: "memory")

// ================= weight pre-rounding =================
__global__ __launch_bounds__(256) void round_kernel(const float* __restrict__ src,
                                                    float* __restrict__ dst, int n4)
{
    int i = blockIdx.x * 256 + threadIdx.x;
    if (i < n4) {
        float4 v = ((const float4*)src)[i];
        v.x = rnd_tf32(v.x); v.y = rnd_tf32(v.y);
        v.z = rnd_tf32(v.z); v.w = rnd_tf32(v.w);
        ((float4*)dst)[i] = v;
    }
}

// ================= tf32 mma GEMM with cp.async 3-stage pipeline =================
// D[m][n] = sum_k A[m][k] * W[n][k] (row-major, K contiguous). A and W pre-rounded tf32.
// MODE 0: QKV scatter (+cq/ck), MODE 1: proj + resid, MODE 2: ff1 + gelu, MODE 3: ff2 + resid
#define TBM 128
#define TBN 128
#define TBK 32
#define TPAD 36
#define STG_BYTES (2 * TBM * TPAD * 4)   // A+B per stage = 36864
#define TC_SMEM   (3 * STG_BYTES)        // 110592

template<int MODE>
__global__ __launch_bounds__(256, 2)
void tc_gemm(const float* __restrict__ A, const float* __restrict__ W,
             const float* __restrict__ bias, const float* __restrict__ resid,
             float* __restrict__ out, int M, int K)
{
    extern __shared__ char smem[];
    const uint32_t sb32 = smem_u32(smem);
    const int tid = threadIdx.x;
    const int wid = tid >> 5, lane = tid & 31;
    const int qr = lane >> 2, qc = lane & 3;
    const int wm = wid >> 2, wn = wid & 3;          // 2 x 4 warp grid
    const int m0 = blockIdx.y * TBM, n0 = blockIdx.x * TBN;

    const int sr  = tid >> 1;
    const int sub = tid & 1;
    const int aok = ((m0 + sr) < M) ? 16 : 0;
    const float* ap = A + (size_t)(m0 + sr) * K + sub * 16;
    const float* bp = W + (size_t)(n0 + sr) * K + sub * 16;
    const uint32_t da = sb32 + (sr * TPAD + sub * 16) * 4;
    const uint32_t db = da + TBM * TPAD * 4;

    float acc[4][4][4];
    #pragma unroll
    for (int i = 0; i < 4; i++)
        #pragma unroll
        for (int j = 0; j < 4; j++)
            #pragma unroll
            for (int t = 0; t < 4; t++) acc[i][j][t] = 0.f;

    const int NC = K / TBK;

    // prologue: stages 0,1
    #pragma unroll
    for (int s = 0; s < 2; s++) {
        #pragma unroll
        for (int q = 0; q < 4; q++) {
            cpa16(da + s * STG_BYTES + q * 16, ap + s * TBK + q * 4, aok);
            cpa16(db + s * STG_BYTES + q * 16, bp + s * TBK + q * 4, 16);
        }
        CP_COMMIT;
    }

    for (int c = 0; c < NC; c++) {
        CP_WAIT1;
        __syncthreads();
        const int st = c % 3;
        const uint32_t* sa  = (const uint32_t*)(smem + st * STG_BYTES);
        const uint32_t* sbp = (const uint32_t*)(smem + st * STG_BYTES + TBM * TPAD * 4);
        #pragma unroll
        for (int ks = 0; ks < 4; ks++) {
            const int k = ks * 8;
            uint32_t afr[4][4], bfr[4][2];
            #pragma unroll
            for (int mt = 0; mt < 4; mt++) {
                int row = wm * 64 + mt * 16 + qr;
                afr[mt][0] = sa[(row    ) * TPAD + k + qc];
                afr[mt][1] = sa[(row + 8) * TPAD + k + qc];
                afr[mt][2] = sa[(row    ) * TPAD + k + qc + 4];
                afr[mt][3] = sa[(row + 8) * TPAD + k + qc + 4];
            }
            #pragma unroll
            for (int nt = 0; nt < 4; nt++) {
                int cn = wn * 32 + nt * 8 + qr;
                bfr[nt][0] = sbp[cn * TPAD + k + qc];
                bfr[nt][1] = sbp[cn * TPAD + k + qc + 4];
            }
            #pragma unroll
            for (int mt = 0; mt < 4; mt++)
                #pragma unroll
                for (int nt = 0; nt < 4; nt++)
                    mma_tf32(acc[mt][nt], afr[mt], bfr[nt]);
        }
        if (c + 2 < NC) {
            const int st2 = (c + 2) % 3;
            const int kk = (c + 2) * TBK;
            #pragma unroll
            for (int q = 0; q < 4; q++) {
                cpa16(da + st2 * STG_BYTES + q * 16, ap + kk + q * 4, aok);
                cpa16(db + st2 * STG_BYTES + q * 16, bp + kk + q * 4, 16);
            }
        }
        CP_COMMIT;
    }

    // ---- epilogue: direct stores with fused op ----
    #pragma unroll
    for (int mt = 0; mt < 4; mt++) {
        int mA = m0 + wm * 64 + mt * 16 + qr;
        #pragma unroll
        for (int nt = 0; nt < 4; nt++) {
            int col = n0 + wn * 32 + nt * 8 + 2 * qc;
            float2 b2 = *(const float2*)&bias[col];
            #pragma unroll
            for (int half = 0; half < 2; half++) {
                int m = mA + half * 8;
                if (m >= M) continue;
                float v0 = acc[mt][nt][half * 2 + 0] + b2.x;
                float v1 = acc[mt][nt][half * 2 + 1] + b2.y;
                if (MODE == 0) {
                    int which = col / DIMC;
                    int r = col - which * DIMC;
                    int bI = m / NTOK, nI = m - bI * NTOK;
                    int h = r >> 6, d = r & 63;
                    float* dst;
                    if (which == 0) {
                        float2 c2 = *(const float2*)&g_cq[bI * DIMC + r];
                        v0 += c2.x; v1 += c2.y; dst = g_q;
                    } else if (which == 1) {
                        float2 c2 = *(const float2*)&g_ck[bI * DIMC + r];
                        v0 += c2.x; v1 += c2.y; dst = g_k;
                    } else dst = g_v;
                    float2 o2 = make_float2(rnd_tf32(v0), rnd_tf32(v1));
                    *(float2*)&dst[((size_t)(bI * HEADS + h) * NTOK + nI) * DHEAD + d] = o2;
                } else if (MODE == 1 || MODE == 3) {
                    size_t ix = (size_t)m * DIMC + col;
                    float2 r2 = *(const float2*)&resid[ix];
                    *(float2*)&out[ix] = make_float2(v0 + r2.x, v1 + r2.y);
                } else { // MODE 2: gelu, rounded (feeds ff2 GEMM)
                    v0 = 0.5f * v0 * (1.0f + erff(v0 * 0.70710678118654752f));
                    v1 = 0.5f * v1 * (1.0f + erff(v1 * 0.70710678118654752f));
                    *(float2*)&out[(size_t)m * FDIM + col] =
                        make_float2(rnd_tf32(v0), rnd_tf32(v1));
                }
            }
        }
    }
}

// ================= fused attention (S = QK^T, softmax, O = PV), tf32 mma =================
#define AQ_STR 68
#define AK_STR 68
#define AV_STR 72
#define AS_STR 212
#define SM_Q 0
#define SM_K (64 * AQ_STR * 4)             // 17408
#define SM_V (SM_K + 200 * AK_STR * 4)     // 71808
#define SM_S (SM_V + 200 * AV_STR * 4)     // 129408
#define ATT_SMEM (SM_S + 64 * AS_STR * 4)  // 183680

__global__ __launch_bounds__(256, 1) void attn_kernel()
{
    extern __shared__ char sm[];
    float* Qs = (float*)(sm + SM_Q);
    float* Ks = (float*)(sm + SM_K);
    float* Vs = (float*)(sm + SM_V);
    float* Ss = (float*)(sm + SM_S);

    const int tid = threadIdx.x;
    const int wid = tid >> 5, lane = tid & 31;
    const int qr = lane >> 2, qc = lane & 3;
    const int bh = blockIdx.y;
    const int m0 = blockIdx.x * 64;

    const float* Qg = g_q + (size_t)bh * NTOK * DHEAD;
    const float* Kg = g_k + (size_t)bh * NTOK * DHEAD;
    const float* Vg = g_v + (size_t)bh * NTOK * DHEAD;

    // ---- load Q tile (64x64), K (200x64), V (200x64) ----
    #pragma unroll
    for (int t = 0; t < 4; t++) {
        int idx = tid + 256 * t;
        int r = idx >> 4, c = (idx & 15) * 4;
        int gr = m0 + r;
        float4 v = (gr < NTOK) ? *(const float4*)&Qg[gr * DHEAD + c]
                               : make_float4(0.f, 0.f, 0.f, 0.f);
        *(float4*)&Qs[r * AQ_STR + c] = v;
    }
    for (int idx = tid; idx < 200 * 16; idx += 256) {
        int r = idx >> 4, c = (idx & 15) * 4;
        float4 kv = (r < NTOK) ? *(const float4*)&Kg[r * DHEAD + c]
                               : make_float4(0.f, 0.f, 0.f, 0.f);
        float4 vv = (r < NTOK) ? *(const float4*)&Vg[r * DHEAD + c]
                               : make_float4(0.f, 0.f, 0.f, 0.f);
        *(float4*)&Ks[r * AK_STR + c] = kv;
        *(float4*)&Vs[r * AV_STR + c] = vv;
    }
    __syncthreads();

    // ---- S = Q K^T * 0.125 (4 m-tiles x 25 n-tiles) ----
    for (int t = wid; t < 100; t += 8) {
        int mt = t / 25, nt = t - mt * 25;
        float acc[4] = {0.f, 0.f, 0.f, 0.f};
        #pragma unroll
        for (int ks = 0; ks < 8; ks++) {
            int k = ks * 8;
            int row = mt * 16 + qr;
            int cn  = nt * 8 + qr;
            uint32_t af[4], bf[2];
            af[0] = __float_as_uint(Qs[row * AQ_STR + k + qc]);
            af[1] = __float_as_uint(Qs[(row + 8) * AQ_STR + k + qc]);
            af[2] = __float_as_uint(Qs[row * AQ_STR + k + qc + 4]);
            af[3] = __float_as_uint(Qs[(row + 8) * AQ_STR + k + qc + 4]);
            bf[0] = __float_as_uint(Ks[cn * AK_STR + k + qc]);
            bf[1] = __float_as_uint(Ks[cn * AK_STR + k + qc + 4]);
            mma_tf32(acc, af, bf);
        }
        int r0 = mt * 16 + qr, c0 = nt * 8 + 2 * qc;
        Ss[r0 * AS_STR + c0]           = acc[0] * 0.125f;
        Ss[r0 * AS_STR + c0 + 1]       = acc[1] * 0.125f;
        Ss[(r0 + 8) * AS_STR + c0]     = acc[2] * 0.125f;
        Ss[(r0 + 8) * AS_STR + c0 + 1] = acc[3] * 0.125f;
    }
    __syncthreads();

    // ---- row softmax (warp per 8 rows), write P tf32-rounded ----
    for (int r = wid * 8; r < wid * 8 + 8; r++) {
        float vbuf[7];
        float mx = -1e30f;
        #pragma unroll
        for (int t = 0; t < 7; t++) {
            int col = lane + 32 * t;
            float v = (col < NTOK) ? Ss[r * AS_STR + col] : -1e30f;
            vbuf[t] = v;
            mx = fmaxf(mx, v);
        }
        #pragma unroll
        for (int o = 16; o > 0; o >>= 1)
            mx = fmaxf(mx, __shfl_xor_sync(0xffffffffu, mx, o));
        float sum = 0.f;
        #pragma unroll
        for (int t = 0; t < 7; t++) {
            int col = lane + 32 * t;
            float e = (col < NTOK) ? expf(vbuf[t] - mx) : 0.f;
            vbuf[t] = e;
            sum += e;
        }
        #pragma unroll
        for (int o = 16; o > 0; o >>= 1)
            sum += __shfl_xor_sync(0xffffffffu, sum, o);
        float inv = 1.0f / sum;
        #pragma unroll
        for (int t = 0; t < 7; t++) {
            int col = lane + 32 * t;
            if (col < 200)
                Ss[r * AS_STR + col] = (col < NTOK) ? rnd_tf32(vbuf[t] * inv) : 0.f;
        }
    }
    __syncthreads();

    // ---- O = P V (4 m-tiles x 8 n-tiles over dh) ----
    const int b = bh / HEADS, h = bh - (bh / HEADS) * HEADS;
    for (int t = wid; t < 32; t += 8) {
        int mt = t >> 3, nt = t & 7;
        float acc[4] = {0.f, 0.f, 0.f, 0.f};
        #pragma unroll
        for (int ks = 0; ks < 25; ks++) {
            int k = ks * 8;
            int row = mt * 16 + qr;
            uint32_t af[4], bf[2];
            af[0] = __float_as_uint(Ss[row * AS_STR + k + qc]);
            af[1] = __float_as_uint(Ss[(row + 8) * AS_STR + k + qc]);
            af[2] = __float_as_uint(Ss[row * AS_STR + k + qc + 4]);
            af[3] = __float_as_uint(Ss[(row + 8) * AS_STR + k + qc + 4]);
            bf[0] = __float_as_uint(Vs[(k + qc) * AV_STR + nt * 8 + qr]);
            bf[1] = __float_as_uint(Vs[(k + qc + 4) * AV_STR + nt * 8 + qr]);
            mma_tf32(acc, af, bf);
        }
        #pragma unroll
        for (int half = 0; half < 2; half++) {
            int gr = m0 + mt * 16 + qr + half * 8;
            if (gr < NTOK) {
                float2 o2 = make_float2(rnd_tf32(acc[half * 2]), rnd_tf32(acc[half * 2 + 1]));
                *(float2*)&g_o[((size_t)(b * NTOK + gr)) * DIMC + h * DHEAD + nt * 8 + 2 * qc] = o2;
            }
        }
    }
}

// ---------------- layernorm (tf32-rounded output) ----------------
__global__ __launch_bounds__(256) void ln_kernel(const float* __restrict__ x,
                                                 const float* __restrict__ w,
                                                 const float* __restrict__ b,
                                                 float* __restrict__ out)
{
    int row = blockIdx.x;
    const float* xr = x + (size_t)row * DIMC;
    float s = 0.f, s2 = 0.f;
    float vals[3];
    #pragma unroll
    for (int t = 0; t < 3; t++) {
        float v = xr[threadIdx.x + 256 * t];
        vals[t] = v; s += v; s2 += v * v;
    }
    __shared__ float shs[8], shs2[8];
    #pragma unroll
    for (int o = 16; o > 0; o >>= 1) {
        s  += __shfl_down_sync(0xffffffffu, s,  o);
        s2 += __shfl_down_sync(0xffffffffu, s2, o);
    }
    if ((threadIdx.x & 31) == 0) { shs[threadIdx.x >> 5] = s; shs2[threadIdx.x >> 5] = s2; }
    __syncthreads();
    __shared__ float sh_mean, sh_rstd;
    if (threadIdx.x == 0) {
        float ts = 0.f, ts2 = 0.f;
        #pragma unroll
        for (int i = 0; i < 8; i++) { ts += shs[i]; ts2 += shs2[i]; }
        float mean = ts / DIMC;
        float var  = ts2 / DIMC - mean * mean;
        sh_mean = mean;
        sh_rstd = rsqrtf(var + EPSLN);
    }
    __syncthreads();
    float mean = sh_mean, rstd = sh_rstd;
    float* orow = out + (size_t)row * DIMC;
    #pragma unroll
    for (int t = 0; t < 3; t++) {
        int i = threadIdx.x + 256 * t;
        orow[i] = rnd_tf32((vals[t] - mean) * rstd * w[i] + b[i]);
    }
}

// ---------------- conv1d (temporal calibration), warp per output ----------------
__global__ __launch_bounds__(256) void conv_kernel(const float* __restrict__ wq,
                                                   const float* __restrict__ bq,
                                                   const float* __restrict__ wk,
                                                   const float* __restrict__ bk)
{
    int gw   = blockIdx.x * 8 + (threadIdx.x >> 5);
    int lane = threadIdx.x & 31;
    int which = gw / (BATCH * DIMC);
    int rem   = gw % (BATCH * DIMC);
    int bt = rem / DIMC;
    int co = rem % DIMC;
    int bv = bt >> 2, t = bt & 3;
    const float* w  = which ? wk : wq;
    const float* bb = which ? bk : bq;
    float s = 0.f;
    const float* h0 = (t > 0) ? (g_h + (size_t)(bv * 4 + t - 1) * NTOK * DIMC) : nullptr;
    const float* h1 = g_h + (size_t)(bv * 4 + t) * NTOK * DIMC;
    const float* h2 = (t < 3) ? (g_h + (size_t)(bv * 4 + t + 1) * NTOK * DIMC) : nullptr;
    for (int ci = lane; ci < DIMC; ci += 32) {
        const float* wp = w + ((size_t)co * DIMC + ci) * 3;
        float w0 = wp[0], w1 = wp[1], w2 = wp[2];
        if (h0) s += w0 * h0[ci];
        s += w1 * h1[ci];
        if (h2) s += w2 * h2[ci];
    }
    #pragma unroll
    for (int o = 16; o > 0; o >>= 1) s += __shfl_down_sync(0xffffffffu, s, o);
    if (lane == 0) {
        float* dst = which ? g_ck : g_cq;
        dst[bt * DIMC + co] = s + bb[co];
    }
}

// ---------------- launch ----------------
extern "C" void kernel_launch(void* const* d_in, const int* in_sizes, int n_in,
                              void* d_out, int out_size)
{
    const float* x      = (const float*)d_in[0];
    const float* ln1_w  = (const float*)d_in[1];
    const float* ln1_b  = (const float*)d_in[2];
    const float* qkv_w  = (const float*)d_in[3];
    const float* qkv_b  = (const float*)d_in[4];
    const float* convq_w= (const float*)d_in[5];
    const float* convq_b= (const float*)d_in[6];
    const float* convk_w= (const float*)d_in[7];
    const float* convk_b= (const float*)d_in[8];
    const float* proj_w = (const float*)d_in[9];
    const float* proj_b = (const float*)d_in[10];
    const float* ln2_w  = (const float*)d_in[11];
    const float* ln2_b  = (const float*)d_in[12];
    const float* ff1_w  = (const float*)d_in[13];
    const float* ff1_b  = (const float*)d_in[14];
    const float* ff2_w  = (const float*)d_in[15];
    const float* ff2_b  = (const float*)d_in[16];
    float* out = (float*)d_out;

    float* p_h;  cudaGetSymbolAddress((void**)&p_h,  g_h);
    float* p_o;  cudaGetSymbolAddress((void**)&p_o,  g_o);
    float* p_x1; cudaGetSymbolAddress((void**)&p_x1, g_x1);
    float* p_ff; cudaGetSymbolAddress((void**)&p_ff, g_ff);
    float* p_w;  cudaGetSymbolAddress((void**)&p_w,  g_wts);

    cudaFuncSetAttribute(tc_gemm<0>, cudaFuncAttributeMaxDynamicSharedMemorySize, TC_SMEM);
    cudaFuncSetAttribute(tc_gemm<1>, cudaFuncAttributeMaxDynamicSharedMemorySize, TC_SMEM);
    cudaFuncSetAttribute(tc_gemm<2>, cudaFuncAttributeMaxDynamicSharedMemorySize, TC_SMEM);
    cudaFuncSetAttribute(tc_gemm<3>, cudaFuncAttributeMaxDynamicSharedMemorySize, TC_SMEM);
    cudaFuncSetAttribute(attn_kernel, cudaFuncAttributeMaxDynamicSharedMemorySize, ATT_SMEM);

    const int MT = (MROWS + TBM - 1) / TBM;   // 99

    // 0. pre-round weights to tf32
    round_kernel<<<(3*DIMC*DIMC/4 + 255)/256, 256>>>(qkv_w,  p_w + W_QKV_OFF,  3*DIMC*DIMC/4);
    round_kernel<<<(DIMC*DIMC/4   + 255)/256, 256>>>(proj_w, p_w + W_PROJ_OFF, DIMC*DIMC/4);
    round_kernel<<<(FDIM*DIMC/4   + 255)/256, 256>>>(ff1_w,  p_w + W_FF1_OFF,  FDIM*DIMC/4);
    round_kernel<<<(DIMC*FDIM/4   + 255)/256, 256>>>(ff2_w,  p_w + W_FF2_OFF,  DIMC*FDIM/4);

    // 1. LN1 (tf32-rounded)
    ln_kernel<<<MROWS, 256>>>(x, ln1_w, ln1_b, p_h);
    // 2. temporal conv on per-frame CLS tokens
    conv_kernel<<<(2 * BATCH * DIMC) / 8, 256>>>(convq_w, convq_b, convk_w, convk_b);
    // 3. QKV GEMM + scatter to head layout (+cq/ck), rounded
    tc_gemm<0><<<dim3(3 * DIMC / TBN, MT), 256, TC_SMEM>>>(
        p_h, p_w + W_QKV_OFF, qkv_b, nullptr, nullptr, MROWS, DIMC);
    // 4. fused attention -> g_o (rounded)
    attn_kernel<<<dim3(4, BATCH * HEADS), 256, ATT_SMEM>>>();
    // 5. proj + residual -> g_x1
    tc_gemm<1><<<dim3(DIMC / TBN, MT), 256, TC_SMEM>>>(
        p_o, p_w + W_PROJ_OFF, proj_b, x, p_x1, MROWS, DIMC);
    // 6. LN2 (tf32-rounded)
    ln_kernel<<<MROWS, 256>>>(p_x1, ln2_w, ln2_b, p_h);
    // 7. FF1 + GELU (rounded)
    tc_gemm<2><<<dim3(FDIM / TBN, MT), 256, TC_SMEM>>>(
        p_h, p_w + W_FF1_OFF, ff1_b, nullptr, p_ff, MROWS, DIMC);
    // 8. FF2 + residual -> out
    tc_gemm<3><<<dim3(DIMC / TBN, MT), 256, TC_SMEM>>>(
        p_ff, p_w + W_FF2_OFF, ff2_b, p_x1, out, MROWS, FDIM);
}